// round 14
// baseline (speedup 1.0000x reference)
#include <cuda_runtime.h>
#include <cstdint>

// Spike-latency encoder:
//   trace:  [B=1024, F=128] f32,  center: [C=8] f32
//   out:    [T=100, B=1024, N=F*C=1024] f32 one-hot along T per (b,n)
//
// out[t,b,f*8+c] = (bin(b,f,c) == t) ? 1.0f : 0.0f
//   bin = trunc( sel(2.5*|trace[b,f]-center[c]|) / 0.1 + 1 )
//   sel(x) = (x > 10.0f) ? 10.1f : x     (bin -> 102, never matches)
//
// 419 MB write stream at the ~6.2 TB/s DRAM write wall. R14: persistent
// single-wave grid (148 SM x 8 CTA = 1184 CTAs), each CTA grid-strides
// over the 20480 (b, tc) tiles of the converged R7 shape — no wave
// transitions, store queue never drains between tiles.

#define BB 1024
#define FF 128
#define CC 8
#define NN 1024
#define TT 100
#define NCH 20          // t-chunks
#define TCH 5           // t-slabs per chunk
#define NTILES (BB * NCH)
#define PGRID (148 * 8) // one full resident wave

__global__ void __launch_bounds__(256, 8)
spike_latency_kernel(const float* __restrict__ trace,
                     const float* __restrict__ center,
                     float* __restrict__ out) {
    const int tid = threadIdx.x;             // 0..255
    const int n0  = tid << 2;                // 4 consecutive n per thread
    const int f   = n0 >> 3;                 // all 4 n share one feature
    const int c0  = n0 & 7;                  // 0 or 4

    // Preload the 4 centers once per CTA lifetime.
    float ct[4];
#pragma unroll
    for (int j = 0; j < 4; j++) ct[j] = __ldg(&center[c0 + j]);

    const size_t stride4 = (size_t)BB * NN / 4;    // 262144 float4 per t-slab

    for (int tile = blockIdx.x; tile < NTILES; tile += PGRID) {
        const int b  = tile & (BB - 1);      // 0..1023 (fast-varying)
        const int tc = tile >> 10;           // 0..19   t-chunk

        const float tv = __ldg(&trace[b * FF + f]);

        int bins[4];
#pragma unroll
        for (int j = 0; j < 4; j++) {
            float tm = 2.5f * fabsf(tv - ct[j]);   // SCALING * |diff|  (f32)
            if (tm > 10.0f) tm = 10.1f;            // cutoff -> TIME_LENGTH + DT
            // trunc(times/DT + 1), IEEE f32 divide (bit-match XLA div.rn:
            // one flipped bin alone would exceed the 1e-3 rel_err budget)
            bins[j] = (int)(__fdiv_rn(tm, 0.1f) + 1.0f);
        }

        float4* outp = reinterpret_cast<float4*>(out + (size_t)b * NN + n0)
                     + (size_t)(tc * TCH) * stride4;

        const int tbase = tc * TCH;
#pragma unroll
        for (int i = 0; i < TCH; i++) {
            const int t = tbase + i;
            float4 v;
            v.x = (bins[0] == t) ? 1.0f : 0.0f;
            v.y = (bins[1] == t) ? 1.0f : 0.0f;
            v.z = (bins[2] == t) ? 1.0f : 0.0f;
            v.w = (bins[3] == t) ? 1.0f : 0.0f;
            __stcs(outp + (size_t)i * stride4, v); // evict-first streaming store
        }
    }
}

extern "C" void kernel_launch(void* const* d_in, const int* in_sizes, int n_in,
                              void* d_out, int out_size) {
    // Identify inputs by element count — robust to metadata ordering:
    //   trace: 131072 floats, center: 8 floats, dummies: 1 each
    const float* trace  = nullptr;
    const float* center = nullptr;
    for (int i = 0; i < n_in; i++) {
        if (in_sizes[i] == BB * FF)     trace  = (const float*)d_in[i];
        else if (in_sizes[i] == CC)     center = (const float*)d_in[i];
    }
    if (!trace)  trace  = (const float*)d_in[0];
    if (!center) center = (const float*)d_in[1];

    float* out = (float*)d_out;  // [100, 1024, 1024] f32 one-hot

    spike_latency_kernel<<<PGRID, 256>>>(trace, center, out);
}

// round 15
// speedup vs baseline: 1.1765x; 1.1765x over previous
#include <cuda_runtime.h>
#include <cstdint>

// Spike-latency encoder (FINAL — converged configuration, R7 winner):
//   trace:  [B=1024, F=128] f32,  center: [C=8] f32
//   out:    [T=100, B=1024, N=F*C=1024] f32 one-hot along T per (b,n)
//
// out[t,b,f*8+c] = (bin(b,f,c) == t) ? 1.0f : 0.0f
//   bin = trunc( sel(2.5*|trace[b,f]-center[c]|) / 0.1 + 1 )
//   sel(x) = (x > 10.0f) ? 10.1f : x     (bin -> 102, never matches)
//
// 419 MB pure write stream at the measured ~6.2 TB/s DRAM write wall.
// Full lever sweep (R3-R14): concurrency saturates at grid~20K (the
// oversubscribed launch IS the store-MLP machine — persistent CTAs
// regress by serializing prologue behind stores); t-split optimum
// NCH=20; 8 CTA/SM; __stcs beats default-policy, v8, and evict_last;
// precompute and CTA-map transpose regress. Floor: 419MB/6.2TB/s ~ 58us.

#define BB 1024
#define FF 128
#define CC 8
#define NN 1024
#define TT 100
#define NCH 20          // t-chunks
#define TCH 5           // t-slabs per chunk

__global__ void __launch_bounds__(256, 8)
spike_latency_kernel(const float* __restrict__ trace,
                     const float* __restrict__ center,
                     float* __restrict__ out) {
    const int b   = blockIdx.x & (BB - 1);   // 0..1023 (fast-varying)
    const int tc  = blockIdx.x >> 10;        // 0..19   t-chunk
    const int tid = threadIdx.x;             // 0..255
    const int n0  = tid << 2;                // 4 consecutive n per thread
    const int f   = n0 >> 3;                 // all 4 n share one feature
    const int c0  = n0 & 7;                  // 0 or 4

    const float tv = __ldg(&trace[b * FF + f]);

    int bins[4];
#pragma unroll
    for (int j = 0; j < 4; j++) {
        float ct = __ldg(&center[c0 + j]);
        float tm = 2.5f * fabsf(tv - ct);          // SCALING * |diff|  (f32)
        if (tm > 10.0f) tm = 10.1f;                // cutoff -> TIME_LENGTH + DT
        // trunc(times/DT + 1), IEEE f32 divide (bit-match XLA div.rn:
        // one flipped bin alone would exceed the 1e-3 rel_err budget)
        bins[j] = (int)(__fdiv_rn(tm, 0.1f) + 1.0f);
    }

    const size_t stride4 = (size_t)BB * NN / 4;    // 262144 float4 per t-slab
    float4* outp = reinterpret_cast<float4*>(out + (size_t)b * NN + n0)
                 + (size_t)(tc * TCH) * stride4;

    const int tbase = tc * TCH;
#pragma unroll
    for (int i = 0; i < TCH; i++) {
        const int t = tbase + i;
        float4 v;
        v.x = (bins[0] == t) ? 1.0f : 0.0f;
        v.y = (bins[1] == t) ? 1.0f : 0.0f;
        v.z = (bins[2] == t) ? 1.0f : 0.0f;
        v.w = (bins[3] == t) ? 1.0f : 0.0f;
        __stcs(outp + (size_t)i * stride4, v);     // evict-first streaming store
    }
}

extern "C" void kernel_launch(void* const* d_in, const int* in_sizes, int n_in,
                              void* d_out, int out_size) {
    // Identify inputs by element count — robust to metadata ordering:
    //   trace: 131072 floats, center: 8 floats, dummies: 1 each
    const float* trace  = nullptr;
    const float* center = nullptr;
    for (int i = 0; i < n_in; i++) {
        if (in_sizes[i] == BB * FF)     trace  = (const float*)d_in[i];
        else if (in_sizes[i] == CC)     center = (const float*)d_in[i];
    }
    if (!trace)  trace  = (const float*)d_in[0];
    if (!center) center = (const float*)d_in[1];

    float* out = (float*)d_out;  // [100, 1024, 1024] f32 one-hot

    spike_latency_kernel<<<BB * NCH, 256>>>(trace, center, out);
}